// round 3
// baseline (speedup 1.0000x reference)
#include <cuda_runtime.h>
#include <math.h>

#define B_    2
#define T_    2048
#define NTOK  4096
#define DIM_  1024
#define HID_  4096
#define NH_   16
#define HD_   64

// Scratch (allocation-free rule: __device__ globals)
__device__ float g_h1 [NTOK * DIM_];
__device__ float g_qkv[NTOK * 3 * DIM_];
__device__ float g_att[NTOK * DIM_];
__device__ float g_x2 [NTOK * DIM_];
__device__ float g_h2 [NTOK * DIM_];
__device__ float g_f1 [NTOK * HID_];

// ---------------------------------------------------------------------------
// LayerNorm: one block per row, 256 threads
// ---------------------------------------------------------------------------
__global__ __launch_bounds__(256) void ln_kernel(
    const float* __restrict__ x, const float* __restrict__ w,
    const float* __restrict__ b, float* __restrict__ y)
{
    int row = blockIdx.x;
    const float* xr = x + (size_t)row * DIM_;
    float s = 0.f, s2 = 0.f;
    for (int i = threadIdx.x; i < DIM_; i += 256) {
        float v = xr[i]; s += v; s2 += v * v;
    }
    __shared__ float rs[8], rs2[8];
    for (int o = 16; o; o >>= 1) {
        s  += __shfl_down_sync(0xffffffffu, s,  o);
        s2 += __shfl_down_sync(0xffffffffu, s2, o);
    }
    int wid = threadIdx.x >> 5, lane = threadIdx.x & 31;
    if (!lane) { rs[wid] = s; rs2[wid] = s2; }
    __syncthreads();
    __shared__ float mu_s, inv_s;
    if (threadIdx.x == 0) {
        float t = 0.f, t2 = 0.f;
        for (int i = 0; i < 8; i++) { t += rs[i]; t2 += rs2[i]; }
        float mu = t / (float)DIM_;
        float var = t2 / (float)DIM_ - mu * mu;
        mu_s = mu;
        inv_s = rsqrtf(var + 1e-5f);
    }
    __syncthreads();
    float mu = mu_s, inv = inv_s;
    float* yr = y + (size_t)row * DIM_;
    for (int i = threadIdx.x; i < DIM_; i += 256)
        yr[i] = (xr[i] - mu) * inv * w[i] + b[i];
}

// ---------------------------------------------------------------------------
// TF32 tensor-core GEMM, double-buffered + register prefetch.
// C[M,N] = A[M,K] * B[K,N] (row-major fp32).
// 128x128 CTA tile, BK=32, 256 threads = 8 warps (2x4), warp tile 64x32.
// EPI: 0 = none, 1 = +bias +residual, 2 = +bias + exact GELU
// ---------------------------------------------------------------------------
__device__ __forceinline__ unsigned f2tf32(float f) {
    unsigned u;
    asm("cvt.rna.tf32.f32 %0, %1;" : "=r"(u) : "f"(f));
    return u;
}

__device__ __forceinline__ void mma_tf32(float* c, const unsigned* a,
                                         const unsigned* b) {
    asm volatile(
        "mma.sync.aligned.m16n8k8.row.col.f32.tf32.tf32.f32 "
        "{%0,%1,%2,%3}, {%4,%5,%6,%7}, {%8,%9}, {%0,%1,%2,%3};"
        : "+f"(c[0]), "+f"(c[1]), "+f"(c[2]), "+f"(c[3])
        : "r"(a[0]), "r"(a[1]), "r"(a[2]), "r"(a[3]),
          "r"(b[0]), "r"(b[1]));
}

#define ASZ (128 * 36)
#define BSZ (32 * 136)
#define STG (ASZ + BSZ)
#define GEMM_SMEM (2 * STG * 4)

template <int EPI>
__global__ __launch_bounds__(256) void gemm_tf32(
    const float* __restrict__ A, const float* __restrict__ Bm,
    const float* __restrict__ bias, const float* __restrict__ res,
    float* __restrict__ C, int M, int N, int K)
{
    extern __shared__ unsigned smu[];

    int tid  = threadIdx.x;
    int lane = tid & 31, warp = tid >> 5;
    int wr = warp >> 2, wc = warp & 3;            // 2x4 warp grid
    int row0 = blockIdx.y * 128, col0 = blockIdx.x * 128;

    int arow = tid >> 3, acol = (tid & 7) * 4;    // A: 32r x 32c per pass
    int brow = tid >> 5, bcol = (tid & 31) * 4;   // B: 8r x 128c per pass

    int g = lane >> 2, t = lane & 3;              // groupID, thread-in-group

    const float* Abase = A  + (size_t)row0 * K;
    const float* Bbase = Bm + col0;

    float acc[4][4][4] = {};
    float4 pa[4], pb[4];

    // ---- prologue: load + store tile 0 into stage 0 ----
#pragma unroll
    for (int i = 0; i < 4; i++)
        pa[i] = *(const float4*)(Abase + (size_t)(i * 32 + arow) * K + acol);
#pragma unroll
    for (int i = 0; i < 4; i++)
        pb[i] = *(const float4*)(Bbase + (size_t)(i * 8 + brow) * N + bcol);
    {
        unsigned* As = smu;
        unsigned* Bs = smu + ASZ;
#pragma unroll
        for (int i = 0; i < 4; i++) {
            int r = i * 32 + arow;
            As[r * 36 + acol + 0] = f2tf32(pa[i].x);
            As[r * 36 + acol + 1] = f2tf32(pa[i].y);
            As[r * 36 + acol + 2] = f2tf32(pa[i].z);
            As[r * 36 + acol + 3] = f2tf32(pa[i].w);
        }
#pragma unroll
        for (int i = 0; i < 4; i++) {
            int r = i * 8 + brow;
            Bs[r * 136 + bcol + 0] = f2tf32(pb[i].x);
            Bs[r * 136 + bcol + 1] = f2tf32(pb[i].y);
            Bs[r * 136 + bcol + 2] = f2tf32(pb[i].z);
            Bs[r * 136 + bcol + 3] = f2tf32(pb[i].w);
        }
    }
    __syncthreads();

    int s = 0;
    for (int kt = 32; kt <= K; kt += 32) {
        bool more = (kt < K);
        // ---- prefetch next tile into registers (overlaps with MMA) ----
        if (more) {
#pragma unroll
            for (int i = 0; i < 4; i++)
                pa[i] = *(const float4*)(Abase +
                            (size_t)(i * 32 + arow) * K + kt + acol);
#pragma unroll
            for (int i = 0; i < 4; i++)
                pb[i] = *(const float4*)(Bbase +
                            (size_t)(kt + i * 8 + brow) * N + bcol);
        }

        // ---- MMA over current stage ----
        const unsigned* As = smu + s * STG;
        const unsigned* Bs = smu + s * STG + ASZ;
#pragma unroll
        for (int ks = 0; ks < 4; ks++) {
            int k0 = ks * 8;
            unsigned af[4][4], bf[4][2];
#pragma unroll
            for (int mt = 0; mt < 4; mt++) {
                int r = wr * 64 + mt * 16 + g;
                af[mt][0] = As[r * 36       + k0 + t];
                af[mt][1] = As[(r + 8) * 36 + k0 + t];
                af[mt][2] = As[r * 36       + k0 + t + 4];
                af[mt][3] = As[(r + 8) * 36 + k0 + t + 4];
            }
#pragma unroll
            for (int nt = 0; nt < 4; nt++) {
                int n = wc * 32 + nt * 8 + g;
                bf[nt][0] = Bs[(k0 + t) * 136     + n];
                bf[nt][1] = Bs[(k0 + t + 4) * 136 + n];
            }
#pragma unroll
            for (int mt = 0; mt < 4; mt++)
#pragma unroll
                for (int nt = 0; nt < 4; nt++)
                    mma_tf32(acc[mt][nt], af[mt], bf[nt]);
        }

        // ---- store prefetched tile into other stage ----
        if (more) {
            unsigned* An = smu + (s ^ 1) * STG;
            unsigned* Bn = An + ASZ;
#pragma unroll
            for (int i = 0; i < 4; i++) {
                int r = i * 32 + arow;
                An[r * 36 + acol + 0] = f2tf32(pa[i].x);
                An[r * 36 + acol + 1] = f2tf32(pa[i].y);
                An[r * 36 + acol + 2] = f2tf32(pa[i].z);
                An[r * 36 + acol + 3] = f2tf32(pa[i].w);
            }
#pragma unroll
            for (int i = 0; i < 4; i++) {
                int r = i * 8 + brow;
                Bn[r * 136 + bcol + 0] = f2tf32(pb[i].x);
                Bn[r * 136 + bcol + 1] = f2tf32(pb[i].y);
                Bn[r * 136 + bcol + 2] = f2tf32(pb[i].z);
                Bn[r * 136 + bcol + 3] = f2tf32(pb[i].w);
            }
        }
        __syncthreads();
        s ^= 1;
    }

    // ---- epilogue ----
#pragma unroll
    for (int mt = 0; mt < 4; mt++) {
#pragma unroll
        for (int nt = 0; nt < 4; nt++) {
            int r = row0 + wr * 64 + mt * 16 + g;
            int c = col0 + wc * 32 + nt * 8 + t * 2;
#pragma unroll
            for (int half = 0; half < 2; half++) {
                int rr = r + half * 8;
                float v0 = acc[mt][nt][half * 2 + 0];
                float v1 = acc[mt][nt][half * 2 + 1];
                if (EPI == 1) {
                    const float* rp = res + (size_t)rr * N + c;
                    v0 += bias[c]     + rp[0];
                    v1 += bias[c + 1] + rp[1];
                } else if (EPI == 2) {
                    v0 += bias[c];
                    v1 += bias[c + 1];
                    v0 = 0.5f * v0 * (1.f + erff(v0 * 0.70710678118654752f));
                    v1 = 0.5f * v1 * (1.f + erff(v1 * 0.70710678118654752f));
                }
                float2 o = make_float2(v0, v1);
                *(float2*)(C + (size_t)rr * N + c) = o;
            }
        }
    }
}

// ---------------------------------------------------------------------------
// Flash-style causal attention with key padding mask (fp32, unchanged).
// ---------------------------------------------------------------------------
__global__ __launch_bounds__(256) void attn_kernel(
    const float* __restrict__ qkv, const int* __restrict__ kpm,
    float* __restrict__ out)
{
    extern __shared__ float sm[];
    float* Qs   = sm;               // [64][64]
    float* Ks   = Qs + 64 * 64;     // [64][65] padded
    float* Vs   = Ks + 64 * 65;     // [64][64]
    float* Ss   = Vs + 64 * 64;     // [64][65] padded
    float* mrow = Ss + 64 * 65;     // [64]
    float* lrow = mrow + 64;        // [64]
    float* arow = lrow + 64;        // [64]
    float* padv = arow + 64;        // [64]
    float* pred = padv + 64;        // [64][4]

    int qb = blockIdx.x, h = blockIdx.y, b = blockIdx.z;
    int tid = threadIdx.x;
    int tx = tid & 15, ty = tid >> 4;
    const float scale = 0.125f;     // 1/sqrt(64)
    const int lds = 3 * DIM_;

    size_t qbase = ((size_t)(b * T_ + qb * 64)) * lds + h * HD_;
    for (int idx = tid; idx < 64 * 16; idx += 256) {
        int r = idx >> 4, c4 = (idx & 15) * 4;
        float4 v = *(const float4*)(qkv + qbase + (size_t)r * lds + c4);
        v.x *= scale; v.y *= scale; v.z *= scale; v.w *= scale;
        *(float4*)&Qs[r * 64 + c4] = v;
    }
    if (tid < 64) { mrow[tid] = -1e30f; lrow[tid] = 0.f; }

    float o[4][4] = {};

    for (int kt = 0; kt <= qb; kt++) {
        __syncthreads();
        size_t kbase = ((size_t)(b * T_ + kt * 64)) * lds + DIM_ + h * HD_;
        size_t vbase = kbase + DIM_;
        for (int idx = tid; idx < 64 * 64; idx += 256) {
            int r = idx >> 6, c = idx & 63;
            Ks[r * 65 + c] = qkv[kbase + (size_t)r * lds + c];
        }
        for (int idx = tid; idx < 64 * 16; idx += 256) {
            int r = idx >> 4, c4 = (idx & 15) * 4;
            *(float4*)&Vs[r * 64 + c4] =
                *(const float4*)(qkv + vbase + (size_t)r * lds + c4);
        }
        if (tid < 64)
            padv[tid] = kpm[b * T_ + kt * 64 + tid] ? -1e9f : 0.f;
        __syncthreads();

        float s[4][4] = {};
#pragma unroll 16
        for (int d = 0; d < 64; d++) {
            float k0 = Ks[(tx * 4 + 0) * 65 + d];
            float k1 = Ks[(tx * 4 + 1) * 65 + d];
            float k2 = Ks[(tx * 4 + 2) * 65 + d];
            float k3 = Ks[(tx * 4 + 3) * 65 + d];
#pragma unroll
            for (int i = 0; i < 4; i++) {
                float q = Qs[(ty * 4 + i) * 64 + d];
                s[i][0] += q * k0; s[i][1] += q * k1;
                s[i][2] += q * k2; s[i][3] += q * k3;
            }
        }
        bool diag = (kt == qb);
#pragma unroll
        for (int i = 0; i < 4; i++) {
            int r = ty * 4 + i;
#pragma unroll
            for (int j = 0; j < 4; j++) {
                int c = tx * 4 + j;
                float v = s[i][j] + padv[c];
                if (diag && c > r) v = -1e30f;
                Ss[r * 65 + c] = v;
            }
        }
        __syncthreads();

        {
            int r = tid >> 2, part = tid & 3, c0 = part * 16;
            float pm = -1e30f;
            for (int c = c0; c < c0 + 16; c++)
                pm = fmaxf(pm, Ss[r * 65 + c]);
            pred[r * 4 + part] = pm;
        }
        __syncthreads();
        if (tid < 64) {
            int r = tid;
            float mn = fmaxf(fmaxf(pred[r*4], pred[r*4+1]),
                             fmaxf(pred[r*4+2], pred[r*4+3]));
            mn = fmaxf(mn, mrow[r]);
            arow[r] = __expf(mrow[r] - mn);
            mrow[r] = mn;
        }
        __syncthreads();
        {
            int r = tid >> 2, part = tid & 3, c0 = part * 16;
            float mn = mrow[r], ps = 0.f;
            for (int c = c0; c < c0 + 16; c++) {
                float p = __expf(Ss[r * 65 + c] - mn);
                Ss[r * 65 + c] = p;
                ps += p;
            }
            pred[r * 4 + part] = ps;
        }
        __syncthreads();
        if (tid < 64) {
            int r = tid;
            lrow[r] = lrow[r] * arow[r] +
                      pred[r*4] + pred[r*4+1] + pred[r*4+2] + pred[r*4+3];
        }
        __syncthreads();

        float al[4];
#pragma unroll
        for (int i = 0; i < 4; i++) al[i] = arow[ty * 4 + i];
#pragma unroll
        for (int i = 0; i < 4; i++) {
            o[i][0] *= al[i]; o[i][1] *= al[i];
            o[i][2] *= al[i]; o[i][3] *= al[i];
        }
#pragma unroll 8
        for (int c = 0; c < 64; c++) {
            float4 v = *(const float4*)&Vs[c * 64 + tx * 4];
#pragma unroll
            for (int i = 0; i < 4; i++) {
                float p = Ss[(ty * 4 + i) * 65 + c];
                o[i][0] += p * v.x; o[i][1] += p * v.y;
                o[i][2] += p * v.z; o[i][3] += p * v.w;
            }
        }
    }

#pragma unroll
    for (int i = 0; i < 4; i++) {
        int r = ty * 4 + i;
        float invl = 1.f / lrow[r];
        size_t ob = ((size_t)(b * T_ + qb * 64 + r)) * DIM_ + h * HD_ + tx * 4;
        out[ob + 0] = o[i][0] * invl;
        out[ob + 1] = o[i][1] * invl;
        out[ob + 2] = o[i][2] * invl;
        out[ob + 3] = o[i][3] * invl;
    }
}

// ---------------------------------------------------------------------------
extern "C" void kernel_launch(void* const* d_in, const int* in_sizes, int n_in,
                              void* d_out, int out_size)
{
    const float* x     = (const float*)d_in[0];
    const int*   kpm   = (const int*)  d_in[1];
    const float* ln1w  = (const float*)d_in[2];
    const float* ln1b  = (const float*)d_in[3];
    const float* qkvw  = (const float*)d_in[4];
    const float* projw = (const float*)d_in[5];
    const float* projb = (const float*)d_in[6];
    const float* ln2w  = (const float*)d_in[7];
    const float* ln2b  = (const float*)d_in[8];
    const float* fc1w  = (const float*)d_in[9];
    const float* fc1b  = (const float*)d_in[10];
    const float* fc2w  = (const float*)d_in[11];
    const float* fc2b  = (const float*)d_in[12];
    float* out = (float*)d_out;

    float *h1, *qkv, *att, *x2, *h2, *f1;
    cudaGetSymbolAddress((void**)&h1,  g_h1);
    cudaGetSymbolAddress((void**)&qkv, g_qkv);
    cudaGetSymbolAddress((void**)&att, g_att);
    cudaGetSymbolAddress((void**)&x2,  g_x2);
    cudaGetSymbolAddress((void**)&h2,  g_h2);
    cudaGetSymbolAddress((void**)&f1,  g_f1);

    const int asmem = 68096;  // attention dynamic smem bytes
    cudaFuncSetAttribute(attn_kernel,
                         cudaFuncAttributeMaxDynamicSharedMemorySize, asmem);
    cudaFuncSetAttribute(gemm_tf32<0>,
                         cudaFuncAttributeMaxDynamicSharedMemorySize, GEMM_SMEM);
    cudaFuncSetAttribute(gemm_tf32<1>,
                         cudaFuncAttributeMaxDynamicSharedMemorySize, GEMM_SMEM);
    cudaFuncSetAttribute(gemm_tf32<2>,
                         cudaFuncAttributeMaxDynamicSharedMemorySize, GEMM_SMEM);

    // 1) LN1
    ln_kernel<<<NTOK, 256>>>(x, ln1w, ln1b, h1);
    // 2) QKV GEMM [4096,1024]x[1024,3072]
    gemm_tf32<0><<<dim3(3 * DIM_ / 128, NTOK / 128), 256, GEMM_SMEM>>>(
        h1, qkvw, nullptr, nullptr, qkv, NTOK, 3 * DIM_, DIM_);
    // 3) Attention
    attn_kernel<<<dim3(T_ / 64, NH_, B_), 256, asmem>>>(qkv, kpm, att);
    // 4) proj GEMM + bias + residual(x)
    gemm_tf32<1><<<dim3(DIM_ / 128, NTOK / 128), 256, GEMM_SMEM>>>(
        att, projw, projb, x, x2, NTOK, DIM_, DIM_);
    // 5) LN2
    ln_kernel<<<NTOK, 256>>>(x2, ln2w, ln2b, h2);
    // 6) fc1 GEMM + bias + exact GELU
    gemm_tf32<2><<<dim3(HID_ / 128, NTOK / 128), 256, GEMM_SMEM>>>(
        h2, fc1w, fc1b, nullptr, f1, NTOK, HID_, DIM_);
    // 7) fc2 GEMM + bias + residual(x2) -> out
    gemm_tf32<1><<<dim3(DIM_ / 128, NTOK / 128), 256, GEMM_SMEM>>>(
        f1, fc2w, fc2b, x2, out, NTOK, DIM_, HID_);
}

// round 4
// speedup vs baseline: 1.1346x; 1.1346x over previous
#include <cuda_runtime.h>
#include <math.h>

#define B_    2
#define T_    2048
#define NTOK  4096
#define DIM_  1024
#define HID_  4096
#define NH_   16
#define HD_   64

// Scratch (allocation-free rule: __device__ globals)
__device__ float g_h1 [NTOK * DIM_];
__device__ float g_qkv[NTOK * 3 * DIM_];
__device__ float g_att[NTOK * DIM_];
__device__ float g_x2 [NTOK * DIM_];
__device__ float g_h2 [NTOK * DIM_];
__device__ float g_f1 [NTOK * HID_];
// tf32-rounded weights
__device__ float g_wq [DIM_ * 3 * DIM_];
__device__ float g_wp [DIM_ * DIM_];
__device__ float g_w1 [DIM_ * HID_];
__device__ float g_w2 [HID_ * DIM_];

__device__ __forceinline__ unsigned f2tf32(float f) {
    unsigned u;
    asm("cvt.rna.tf32.f32 %0, %1;" : "=r"(u) : "f"(f));
    return u;
}
__device__ __forceinline__ float rtf32(float f) {
    return __uint_as_float(f2tf32(f));
}

// ---------------------------------------------------------------------------
// Elementwise tf32 rounding (weights), float4 vectorized
// ---------------------------------------------------------------------------
__global__ __launch_bounds__(256) void round4_kernel(
    const float* __restrict__ in, float* __restrict__ out, int n4)
{
    int i = blockIdx.x * 256 + threadIdx.x;
    if (i < n4) {
        float4 v = ((const float4*)in)[i];
        v.x = rtf32(v.x); v.y = rtf32(v.y);
        v.z = rtf32(v.z); v.w = rtf32(v.w);
        ((float4*)out)[i] = v;
    }
}

// ---------------------------------------------------------------------------
// LayerNorm: one block per row, 256 threads. Output rounded to tf32
// (it only feeds GEMM A operands).
// ---------------------------------------------------------------------------
__global__ __launch_bounds__(256) void ln_kernel(
    const float* __restrict__ x, const float* __restrict__ w,
    const float* __restrict__ b, float* __restrict__ y)
{
    int row = blockIdx.x;
    const float* xr = x + (size_t)row * DIM_;
    float s = 0.f, s2 = 0.f;
    for (int i = threadIdx.x; i < DIM_; i += 256) {
        float v = xr[i]; s += v; s2 += v * v;
    }
    __shared__ float rs[8], rs2[8];
    for (int o = 16; o; o >>= 1) {
        s  += __shfl_down_sync(0xffffffffu, s,  o);
        s2 += __shfl_down_sync(0xffffffffu, s2, o);
    }
    int wid = threadIdx.x >> 5, lane = threadIdx.x & 31;
    if (!lane) { rs[wid] = s; rs2[wid] = s2; }
    __syncthreads();
    __shared__ float mu_s, inv_s;
    if (threadIdx.x == 0) {
        float t = 0.f, t2 = 0.f;
        for (int i = 0; i < 8; i++) { t += rs[i]; t2 += rs2[i]; }
        float mu = t / (float)DIM_;
        float var = t2 / (float)DIM_ - mu * mu;
        mu_s = mu;
        inv_s = rsqrtf(var + 1e-5f);
    }
    __syncthreads();
    float mu = mu_s, inv = inv_s;
    float* yr = y + (size_t)row * DIM_;
    for (int i = threadIdx.x; i < DIM_; i += 256)
        yr[i] = rtf32((xr[i] - mu) * inv * w[i] + b[i]);
}

// ---------------------------------------------------------------------------
// TF32 HMMA GEMM, cp.async 3-stage pipeline.
// CTA tile 128x256, BK=16, 8 warps (2x4), warp tile 64x64.
// Inputs MUST be pre-rounded to tf32 (raw bits fed to mma).
// EPI: 0 none | 1 +bias+residual | 2 +bias+GELU (output rounded to tf32)
// ---------------------------------------------------------------------------
__device__ __forceinline__ void mma_tf32(float* c, const unsigned* a,
                                         const unsigned* b) {
    asm volatile(
        "mma.sync.aligned.m16n8k8.row.col.f32.tf32.tf32.f32 "
        "{%0,%1,%2,%3}, {%4,%5,%6,%7}, {%8,%9}, {%0,%1,%2,%3};"
        : "+f"(c[0]), "+f"(c[1]), "+f"(c[2]), "+f"(c[3])
        : "r"(a[0]), "r"(a[1]), "r"(a[2]), "r"(a[3]),
          "r"(b[0]), "r"(b[1]));
}

#define BM 128
#define BN 256
#define BKk 16
#define ASTR 20
#define BSTR 264
#define SA (BM * ASTR)          // 2560 words
#define SB (BKk * BSTR)         // 4224 words
#define SW (SA + SB)            // 6784 words
#define NSTAGE 3
#define GEMM_SMEM (NSTAGE * SW * 4)   // 81408 B

#define CPASYNC16(dst, src) \
    asm volatile("cp.async.cg.shared.global [%0], [%1], 16;" \
                 :: "r"(dst), "l"(src))

template <int EPI>
__global__ __launch_bounds__(256, 1) void gemm_tc(
    const float* __restrict__ A, const float* __restrict__ Bm,
    const float* __restrict__ bias, const float* __restrict__ res,
    float* __restrict__ C, int M, int N, int K)
{
    extern __shared__ float smf[];
    unsigned sbase = (unsigned)__cvta_generic_to_shared(smf);

    int tid = threadIdx.x, lane = tid & 31, warp = tid >> 5;
    int wr = warp >> 2, wc = warp & 3;       // 2x4 warp grid, 64x64 each
    int row0 = blockIdx.y * BM, col0 = blockIdx.x * BN;
    int g = lane >> 2, t = lane & 3;

    const float* Ab = A + (size_t)row0 * K;
    const float* Bb = Bm + col0;

    // producer mapping
    int a_row = tid >> 2,            a_col = (tid & 3) * 4;    // + row+64
    int b_rb  = tid >> 6,            b_col = (tid & 63) * 4;   // rows b_rb+4p

    float acc[4][8][4] = {};

    int iters = K / BKk;

    // ---- prologue: fill stages 0..NSTAGE-2 ----
#pragma unroll
    for (int s = 0; s < NSTAGE - 1; s++) {
        int kt = s * BKk;
        unsigned sa = sbase + (unsigned)(s * SW) * 4u;
        unsigned sb = sa + SA * 4u;
        CPASYNC16(sa + (unsigned)(a_row * ASTR + a_col) * 4u,
                  Ab + (size_t)a_row * K + kt + a_col);
        CPASYNC16(sa + (unsigned)((a_row + 64) * ASTR + a_col) * 4u,
                  Ab + (size_t)(a_row + 64) * K + kt + a_col);
#pragma unroll
        for (int p = 0; p < 4; p++) {
            int r = b_rb + 4 * p;
            CPASYNC16(sb + (unsigned)(r * BSTR + b_col) * 4u,
                      Bb + (size_t)(kt + r) * N + b_col);
        }
        asm volatile("cp.async.commit_group;");
    }

    for (int it = 0; it < iters; it++) {
        asm volatile("cp.async.wait_group 1;");
        __syncthreads();

        // issue load for stage it+NSTAGE-1 (overlaps with MMA below)
        int nk = it + NSTAGE - 1;
        if (nk < iters) {
            int st = nk % NSTAGE;
            int kt = nk * BKk;
            unsigned sa = sbase + (unsigned)(st * SW) * 4u;
            unsigned sb = sa + SA * 4u;
            CPASYNC16(sa + (unsigned)(a_row * ASTR + a_col) * 4u,
                      Ab + (size_t)a_row * K + kt + a_col);
            CPASYNC16(sa + (unsigned)((a_row + 64) * ASTR + a_col) * 4u,
                      Ab + (size_t)(a_row + 64) * K + kt + a_col);
#pragma unroll
            for (int p = 0; p < 4; p++) {
                int r = b_rb + 4 * p;
                CPASYNC16(sb + (unsigned)(r * BSTR + b_col) * 4u,
                          Bb + (size_t)(kt + r) * N + b_col);
            }
        }
        asm volatile("cp.async.commit_group;");

        // ---- MMA on stage it%NSTAGE ----
        const unsigned* As = (const unsigned*)(smf + (it % NSTAGE) * SW);
        const unsigned* Bs = As + SA;
#pragma unroll
        for (int ks = 0; ks < 2; ks++) {
            int k0 = ks * 8;
            unsigned af[4][4], bf[8][2];
#pragma unroll
            for (int mt = 0; mt < 4; mt++) {
                int r = wr * 64 + mt * 16 + g;
                af[mt][0] = As[r * ASTR       + k0 + t];
                af[mt][1] = As[(r + 8) * ASTR + k0 + t];
                af[mt][2] = As[r * ASTR       + k0 + t + 4];
                af[mt][3] = As[(r + 8) * ASTR + k0 + t + 4];
            }
#pragma unroll
            for (int nt = 0; nt < 8; nt++) {
                int n = wc * 64 + nt * 8 + g;
                bf[nt][0] = Bs[(k0 + t) * BSTR     + n];
                bf[nt][1] = Bs[(k0 + t + 4) * BSTR + n];
            }
#pragma unroll
            for (int mt = 0; mt < 4; mt++)
#pragma unroll
                for (int nt = 0; nt < 8; nt++)
                    mma_tf32(acc[mt][nt], af[mt], bf[nt]);
        }
    }

    // ---- epilogue ----
#pragma unroll
    for (int mt = 0; mt < 4; mt++) {
#pragma unroll
        for (int nt = 0; nt < 8; nt++) {
            int r = row0 + wr * 64 + mt * 16 + g;
            int c = col0 + wc * 64 + nt * 8 + t * 2;
#pragma unroll
            for (int half = 0; half < 2; half++) {
                int rr = r + half * 8;
                float v0 = acc[mt][nt][half * 2 + 0];
                float v1 = acc[mt][nt][half * 2 + 1];
                if (EPI == 1) {
                    const float* rp = res + (size_t)rr * N + c;
                    v0 += bias[c]     + rp[0];
                    v1 += bias[c + 1] + rp[1];
                } else if (EPI == 2) {
                    v0 += bias[c];
                    v1 += bias[c + 1];
                    v0 = 0.5f * v0 * (1.f + erff(v0 * 0.70710678118654752f));
                    v1 = 0.5f * v1 * (1.f + erff(v1 * 0.70710678118654752f));
                    v0 = rtf32(v0);   // feeds fc2 GEMM
                    v1 = rtf32(v1);
                }
                *(float2*)(C + (size_t)rr * N + c) = make_float2(v0, v1);
            }
        }
    }
}

// ---------------------------------------------------------------------------
// Flash-style causal attention with key padding mask (fp32).
// Output rounded to tf32 (feeds proj GEMM only).
// ---------------------------------------------------------------------------
__global__ __launch_bounds__(256) void attn_kernel(
    const float* __restrict__ qkv, const int* __restrict__ kpm,
    float* __restrict__ out)
{
    extern __shared__ float sm[];
    float* Qs   = sm;               // [64][64]
    float* Ks   = Qs + 64 * 64;     // [64][65] padded
    float* Vs   = Ks + 64 * 65;     // [64][64]
    float* Ss   = Vs + 64 * 64;     // [64][65] padded
    float* mrow = Ss + 64 * 65;
    float* lrow = mrow + 64;
    float* arow = lrow + 64;
    float* padv = arow + 64;
    float* pred = padv + 64;        // [64][4]

    int qb = blockIdx.x, h = blockIdx.y, b = blockIdx.z;
    int tid = threadIdx.x;
    int tx = tid & 15, ty = tid >> 4;
    const float scale = 0.125f;
    const int lds = 3 * DIM_;

    size_t qbase = ((size_t)(b * T_ + qb * 64)) * lds + h * HD_;
    for (int idx = tid; idx < 64 * 16; idx += 256) {
        int r = idx >> 4, c4 = (idx & 15) * 4;
        float4 v = *(const float4*)(qkv + qbase + (size_t)r * lds + c4);
        v.x *= scale; v.y *= scale; v.z *= scale; v.w *= scale;
        *(float4*)&Qs[r * 64 + c4] = v;
    }
    if (tid < 64) { mrow[tid] = -1e30f; lrow[tid] = 0.f; }

    float o[4][4] = {};

    for (int kt = 0; kt <= qb; kt++) {
        __syncthreads();
        size_t kbase = ((size_t)(b * T_ + kt * 64)) * lds + DIM_ + h * HD_;
        size_t vbase = kbase + DIM_;
        for (int idx = tid; idx < 64 * 64; idx += 256) {
            int r = idx >> 6, c = idx & 63;
            Ks[r * 65 + c] = qkv[kbase + (size_t)r * lds + c];
        }
        for (int idx = tid; idx < 64 * 16; idx += 256) {
            int r = idx >> 4, c4 = (idx & 15) * 4;
            *(float4*)&Vs[r * 64 + c4] =
                *(const float4*)(qkv + vbase + (size_t)r * lds + c4);
        }
        if (tid < 64)
            padv[tid] = kpm[b * T_ + kt * 64 + tid] ? -1e9f : 0.f;
        __syncthreads();

        float s[4][4] = {};
#pragma unroll 16
        for (int d = 0; d < 64; d++) {
            float k0 = Ks[(tx * 4 + 0) * 65 + d];
            float k1 = Ks[(tx * 4 + 1) * 65 + d];
            float k2 = Ks[(tx * 4 + 2) * 65 + d];
            float k3 = Ks[(tx * 4 + 3) * 65 + d];
#pragma unroll
            for (int i = 0; i < 4; i++) {
                float q = Qs[(ty * 4 + i) * 64 + d];
                s[i][0] += q * k0; s[i][1] += q * k1;
                s[i][2] += q * k2; s[i][3] += q * k3;
            }
        }
        bool diag = (kt == qb);
#pragma unroll
        for (int i = 0; i < 4; i++) {
            int r = ty * 4 + i;
#pragma unroll
            for (int j = 0; j < 4; j++) {
                int c = tx * 4 + j;
                float v = s[i][j] + padv[c];
                if (diag && c > r) v = -1e30f;
                Ss[r * 65 + c] = v;
            }
        }
        __syncthreads();

        {
            int r = tid >> 2, part = tid & 3, c0 = part * 16;
            float pm = -1e30f;
            for (int c = c0; c < c0 + 16; c++)
                pm = fmaxf(pm, Ss[r * 65 + c]);
            pred[r * 4 + part] = pm;
        }
        __syncthreads();
        if (tid < 64) {
            int r = tid;
            float mn = fmaxf(fmaxf(pred[r*4], pred[r*4+1]),
                             fmaxf(pred[r*4+2], pred[r*4+3]));
            mn = fmaxf(mn, mrow[r]);
            arow[r] = __expf(mrow[r] - mn);
            mrow[r] = mn;
        }
        __syncthreads();
        {
            int r = tid >> 2, part = tid & 3, c0 = part * 16;
            float mn = mrow[r], ps = 0.f;
            for (int c = c0; c < c0 + 16; c++) {
                float p = __expf(Ss[r * 65 + c] - mn);
                Ss[r * 65 + c] = p;
                ps += p;
            }
            pred[r * 4 + part] = ps;
        }
        __syncthreads();
        if (tid < 64) {
            int r = tid;
            lrow[r] = lrow[r] * arow[r] +
                      pred[r*4] + pred[r*4+1] + pred[r*4+2] + pred[r*4+3];
        }
        __syncthreads();

        float al[4];
#pragma unroll
        for (int i = 0; i < 4; i++) al[i] = arow[ty * 4 + i];
#pragma unroll
        for (int i = 0; i < 4; i++) {
            o[i][0] *= al[i]; o[i][1] *= al[i];
            o[i][2] *= al[i]; o[i][3] *= al[i];
        }
#pragma unroll 8
        for (int c = 0; c < 64; c++) {
            float4 v = *(const float4*)&Vs[c * 64 + tx * 4];
#pragma unroll
            for (int i = 0; i < 4; i++) {
                float p = Ss[(ty * 4 + i) * 65 + c];
                o[i][0] += p * v.x; o[i][1] += p * v.y;
                o[i][2] += p * v.z; o[i][3] += p * v.w;
            }
        }
    }

#pragma unroll
    for (int i = 0; i < 4; i++) {
        int r = ty * 4 + i;
        float invl = 1.f / lrow[r];
        size_t ob = ((size_t)(b * T_ + qb * 64 + r)) * DIM_ + h * HD_ + tx * 4;
        out[ob + 0] = rtf32(o[i][0] * invl);
        out[ob + 1] = rtf32(o[i][1] * invl);
        out[ob + 2] = rtf32(o[i][2] * invl);
        out[ob + 3] = rtf32(o[i][3] * invl);
    }
}

// ---------------------------------------------------------------------------
extern "C" void kernel_launch(void* const* d_in, const int* in_sizes, int n_in,
                              void* d_out, int out_size)
{
    const float* x     = (const float*)d_in[0];
    const int*   kpm   = (const int*)  d_in[1];
    const float* ln1w  = (const float*)d_in[2];
    const float* ln1b  = (const float*)d_in[3];
    const float* qkvw  = (const float*)d_in[4];
    const float* projw = (const float*)d_in[5];
    const float* projb = (const float*)d_in[6];
    const float* ln2w  = (const float*)d_in[7];
    const float* ln2b  = (const float*)d_in[8];
    const float* fc1w  = (const float*)d_in[9];
    const float* fc1b  = (const float*)d_in[10];
    const float* fc2w  = (const float*)d_in[11];
    const float* fc2b  = (const float*)d_in[12];
    float* out = (float*)d_out;

    float *h1, *qkv, *att, *x2, *h2, *f1, *wq, *wp, *w1, *w2;
    cudaGetSymbolAddress((void**)&h1,  g_h1);
    cudaGetSymbolAddress((void**)&qkv, g_qkv);
    cudaGetSymbolAddress((void**)&att, g_att);
    cudaGetSymbolAddress((void**)&x2,  g_x2);
    cudaGetSymbolAddress((void**)&h2,  g_h2);
    cudaGetSymbolAddress((void**)&f1,  g_f1);
    cudaGetSymbolAddress((void**)&wq,  g_wq);
    cudaGetSymbolAddress((void**)&wp,  g_wp);
    cudaGetSymbolAddress((void**)&w1,  g_w1);
    cudaGetSymbolAddress((void**)&w2,  g_w2);

    const int asmem = 68096;
    cudaFuncSetAttribute(attn_kernel,
                         cudaFuncAttributeMaxDynamicSharedMemorySize, asmem);
    cudaFuncSetAttribute(gemm_tc<0>,
                         cudaFuncAttributeMaxDynamicSharedMemorySize, GEMM_SMEM);
    cudaFuncSetAttribute(gemm_tc<1>,
                         cudaFuncAttributeMaxDynamicSharedMemorySize, GEMM_SMEM);
    cudaFuncSetAttribute(gemm_tc<2>,
                         cudaFuncAttributeMaxDynamicSharedMemorySize, GEMM_SMEM);

    // 0) round weights to tf32
    round4_kernel<<<(DIM_*3*DIM_/4 + 255)/256, 256>>>(qkvw, wq, DIM_*3*DIM_/4);
    round4_kernel<<<(DIM_*DIM_/4   + 255)/256, 256>>>(projw, wp, DIM_*DIM_/4);
    round4_kernel<<<(DIM_*HID_/4   + 255)/256, 256>>>(fc1w,  w1, DIM_*HID_/4);
    round4_kernel<<<(HID_*DIM_/4   + 255)/256, 256>>>(fc2w,  w2, HID_*DIM_/4);

    // 1) LN1 (output tf32-rounded)
    ln_kernel<<<NTOK, 256>>>(x, ln1w, ln1b, h1);
    // 2) QKV GEMM [4096,1024]x[1024,3072]
    gemm_tc<0><<<dim3(3 * DIM_ / BN, NTOK / BM), 256, GEMM_SMEM>>>(
        h1, wq, nullptr, nullptr, qkv, NTOK, 3 * DIM_, DIM_);
    // 3) Attention (output tf32-rounded)
    attn_kernel<<<dim3(T_ / 64, NH_, B_), 256, asmem>>>(qkv, kpm, att);
    // 4) proj GEMM + bias + residual(x)
    gemm_tc<1><<<dim3(DIM_ / BN, NTOK / BM), 256, GEMM_SMEM>>>(
        att, wp, projb, x, x2, NTOK, DIM_, DIM_);
    // 5) LN2 (output tf32-rounded)
    ln_kernel<<<NTOK, 256>>>(x2, ln2w, ln2b, h2);
    // 6) fc1 GEMM + bias + GELU (output tf32-rounded)
    gemm_tc<2><<<dim3(HID_ / BN, NTOK / BM), 256, GEMM_SMEM>>>(
        h2, w1, fc1b, nullptr, f1, NTOK, HID_, DIM_);
    // 7) fc2 GEMM + bias + residual(x2) -> out
    gemm_tc<1><<<dim3(DIM_ / BN, NTOK / BM), 256, GEMM_SMEM>>>(
        f1, w2, fc2b, x2, out, NTOK, DIM_, HID_);
}

// round 5
// speedup vs baseline: 1.5986x; 1.4089x over previous
#include <cuda_runtime.h>
#include <math.h>

#define B_    2
#define T_    2048
#define NTOK  4096
#define DIM_  1024
#define HID_  4096
#define NH_   16
#define HD_   64

// Scratch (allocation-free rule: __device__ globals)
__device__ float g_h1 [NTOK * DIM_];
__device__ float g_qkv[NTOK * 3 * DIM_];
__device__ float g_att[NTOK * DIM_];
__device__ float g_x2 [NTOK * DIM_];
__device__ float g_h2 [NTOK * DIM_];
__device__ float g_f1 [NTOK * HID_];
// tf32-rounded weights
__device__ float g_wq [DIM_ * 3 * DIM_];
__device__ float g_wp [DIM_ * DIM_];
__device__ float g_w1 [DIM_ * HID_];
__device__ float g_w2 [HID_ * DIM_];

__device__ __forceinline__ unsigned f2tf32(float f) {
    unsigned u;
    asm("cvt.rna.tf32.f32 %0, %1;" : "=r"(u) : "f"(f));
    return u;
}
__device__ __forceinline__ float rtf32(float f) {
    return __uint_as_float(f2tf32(f));
}

// ---------------------------------------------------------------------------
// Elementwise tf32 rounding (weights), float4 vectorized
// ---------------------------------------------------------------------------
__global__ __launch_bounds__(256) void round4_kernel(
    const float* __restrict__ in, float* __restrict__ out, int n4)
{
    int i = blockIdx.x * 256 + threadIdx.x;
    if (i < n4) {
        float4 v = ((const float4*)in)[i];
        v.x = rtf32(v.x); v.y = rtf32(v.y);
        v.z = rtf32(v.z); v.w = rtf32(v.w);
        ((float4*)out)[i] = v;
    }
}

// ---------------------------------------------------------------------------
// LayerNorm: one block per row, 256 threads. Output rounded to tf32.
// ---------------------------------------------------------------------------
__global__ __launch_bounds__(256) void ln_kernel(
    const float* __restrict__ x, const float* __restrict__ w,
    const float* __restrict__ b, float* __restrict__ y)
{
    int row = blockIdx.x;
    const float* xr = x + (size_t)row * DIM_;
    float s = 0.f, s2 = 0.f;
    for (int i = threadIdx.x; i < DIM_; i += 256) {
        float v = xr[i]; s += v; s2 += v * v;
    }
    __shared__ float rs[8], rs2[8];
    for (int o = 16; o; o >>= 1) {
        s  += __shfl_down_sync(0xffffffffu, s,  o);
        s2 += __shfl_down_sync(0xffffffffu, s2, o);
    }
    int wid = threadIdx.x >> 5, lane = threadIdx.x & 31;
    if (!lane) { rs[wid] = s; rs2[wid] = s2; }
    __syncthreads();
    __shared__ float mu_s, inv_s;
    if (threadIdx.x == 0) {
        float t = 0.f, t2 = 0.f;
        for (int i = 0; i < 8; i++) { t += rs[i]; t2 += rs2[i]; }
        float mu = t / (float)DIM_;
        float var = t2 / (float)DIM_ - mu * mu;
        mu_s = mu;
        inv_s = rsqrtf(var + 1e-5f);
    }
    __syncthreads();
    float mu = mu_s, inv = inv_s;
    float* yr = y + (size_t)row * DIM_;
    for (int i = threadIdx.x; i < DIM_; i += 256)
        yr[i] = rtf32((xr[i] - mu) * inv * w[i] + b[i]);
}

// ---------------------------------------------------------------------------
// TF32 HMMA GEMM, cp.async 3-stage pipeline (unchanged from R4).
// ---------------------------------------------------------------------------
__device__ __forceinline__ void mma_tf32(float* c, const unsigned* a,
                                         const unsigned* b) {
    asm volatile(
        "mma.sync.aligned.m16n8k8.row.col.f32.tf32.tf32.f32 "
        "{%0,%1,%2,%3}, {%4,%5,%6,%7}, {%8,%9}, {%0,%1,%2,%3};"
        : "+f"(c[0]), "+f"(c[1]), "+f"(c[2]), "+f"(c[3])
        : "r"(a[0]), "r"(a[1]), "r"(a[2]), "r"(a[3]),
          "r"(b[0]), "r"(b[1]));
}

#define BM 128
#define BN 256
#define BKk 16
#define ASTR 20
#define BSTR 264
#define SA (BM * ASTR)
#define SB (BKk * BSTR)
#define SW (SA + SB)
#define NSTAGE 3
#define GEMM_SMEM (NSTAGE * SW * 4)

#define CPASYNC16(dst, src) \
    asm volatile("cp.async.cg.shared.global [%0], [%1], 16;" \
                 :: "r"(dst), "l"(src))

template <int EPI>
__global__ __launch_bounds__(256, 1) void gemm_tc(
    const float* __restrict__ A, const float* __restrict__ Bm,
    const float* __restrict__ bias, const float* __restrict__ res,
    float* __restrict__ C, int M, int N, int K)
{
    extern __shared__ float smf[];
    unsigned sbase = (unsigned)__cvta_generic_to_shared(smf);

    int tid = threadIdx.x, lane = tid & 31, warp = tid >> 5;
    int wr = warp >> 2, wc = warp & 3;
    int row0 = blockIdx.y * BM, col0 = blockIdx.x * BN;
    int g = lane >> 2, t = lane & 3;

    const float* Ab = A + (size_t)row0 * K;
    const float* Bb = Bm + col0;

    int a_row = tid >> 2, a_col = (tid & 3) * 4;
    int b_rb  = tid >> 6, b_col = (tid & 63) * 4;

    float acc[4][8][4] = {};
    int iters = K / BKk;

#pragma unroll
    for (int s = 0; s < NSTAGE - 1; s++) {
        int kt = s * BKk;
        unsigned sa = sbase + (unsigned)(s * SW) * 4u;
        unsigned sb = sa + SA * 4u;
        CPASYNC16(sa + (unsigned)(a_row * ASTR + a_col) * 4u,
                  Ab + (size_t)a_row * K + kt + a_col);
        CPASYNC16(sa + (unsigned)((a_row + 64) * ASTR + a_col) * 4u,
                  Ab + (size_t)(a_row + 64) * K + kt + a_col);
#pragma unroll
        for (int p = 0; p < 4; p++) {
            int r = b_rb + 4 * p;
            CPASYNC16(sb + (unsigned)(r * BSTR + b_col) * 4u,
                      Bb + (size_t)(kt + r) * N + b_col);
        }
        asm volatile("cp.async.commit_group;");
    }

    for (int it = 0; it < iters; it++) {
        asm volatile("cp.async.wait_group 1;");
        __syncthreads();

        int nk = it + NSTAGE - 1;
        if (nk < iters) {
            int st = nk % NSTAGE;
            int kt = nk * BKk;
            unsigned sa = sbase + (unsigned)(st * SW) * 4u;
            unsigned sb = sa + SA * 4u;
            CPASYNC16(sa + (unsigned)(a_row * ASTR + a_col) * 4u,
                      Ab + (size_t)a_row * K + kt + a_col);
            CPASYNC16(sa + (unsigned)((a_row + 64) * ASTR + a_col) * 4u,
                      Ab + (size_t)(a_row + 64) * K + kt + a_col);
#pragma unroll
            for (int p = 0; p < 4; p++) {
                int r = b_rb + 4 * p;
                CPASYNC16(sb + (unsigned)(r * BSTR + b_col) * 4u,
                          Bb + (size_t)(kt + r) * N + b_col);
            }
        }
        asm volatile("cp.async.commit_group;");

        const unsigned* As = (const unsigned*)(smf + (it % NSTAGE) * SW);
        const unsigned* Bs = As + SA;
#pragma unroll
        for (int ks = 0; ks < 2; ks++) {
            int k0 = ks * 8;
            unsigned af[4][4], bf[8][2];
#pragma unroll
            for (int mt = 0; mt < 4; mt++) {
                int r = wr * 64 + mt * 16 + g;
                af[mt][0] = As[r * ASTR       + k0 + t];
                af[mt][1] = As[(r + 8) * ASTR + k0 + t];
                af[mt][2] = As[r * ASTR       + k0 + t + 4];
                af[mt][3] = As[(r + 8) * ASTR + k0 + t + 4];
            }
#pragma unroll
            for (int nt = 0; nt < 8; nt++) {
                int n = wc * 64 + nt * 8 + g;
                bf[nt][0] = Bs[(k0 + t) * BSTR     + n];
                bf[nt][1] = Bs[(k0 + t + 4) * BSTR + n];
            }
#pragma unroll
            for (int mt = 0; mt < 4; mt++)
#pragma unroll
                for (int nt = 0; nt < 8; nt++)
                    mma_tf32(acc[mt][nt], af[mt], bf[nt]);
        }
    }

#pragma unroll
    for (int mt = 0; mt < 4; mt++) {
#pragma unroll
        for (int nt = 0; nt < 8; nt++) {
            int r = row0 + wr * 64 + mt * 16 + g;
            int c = col0 + wc * 64 + nt * 8 + t * 2;
#pragma unroll
            for (int half = 0; half < 2; half++) {
                int rr = r + half * 8;
                float v0 = acc[mt][nt][half * 2 + 0];
                float v1 = acc[mt][nt][half * 2 + 1];
                if (EPI == 1) {
                    const float* rp = res + (size_t)rr * N + c;
                    v0 += bias[c]     + rp[0];
                    v1 += bias[c + 1] + rp[1];
                } else if (EPI == 2) {
                    v0 += bias[c];
                    v1 += bias[c + 1];
                    v0 = 0.5f * v0 * (1.f + erff(v0 * 0.70710678118654752f));
                    v1 = 0.5f * v1 * (1.f + erff(v1 * 0.70710678118654752f));
                    v0 = rtf32(v0);
                    v1 = rtf32(v1);
                }
                *(float2*)(C + (size_t)rr * N + c) = make_float2(v0, v1);
            }
        }
    }
}

// ---------------------------------------------------------------------------
// Tensor-core flash attention (tf32 HMMA), causal + key-padding mask.
// Q tile 128 rows, K/V tiles 64 tokens. 4 warps: warp w owns q-rows
// [32w, 32w+32) as two m16 tiles. Softmax in fp32 registers.
// Smem strides 72 words -> all frag LDS/STS bank-conflict-free.
// ---------------------------------------------------------------------------
#define QT 128
#define KT 64
#define AST 72
#define ATTN_SMEM ((QT*AST + KT*AST + KT*AST + QT*AST + KT) * 4)

__global__ __launch_bounds__(128, 1) void attn_tc(
    const float* __restrict__ qkv, const int* __restrict__ kpm,
    float* __restrict__ out)
{
    extern __shared__ float sm[];
    float* Qs   = sm;                    // [128][72] tf32(Q*scale)
    float* Kt   = Qs + QT * AST;         // [64 d][72 tok] transposed K
    float* Vs   = Kt + KT * AST;         // [64 tok][72 d]
    float* Ps   = Vs + KT * AST;         // [128][72] probabilities
    float* padv = Ps + QT * AST;         // [64]

    int qb = blockIdx.x, h = blockIdx.y, b = blockIdx.z;
    int tid = threadIdx.x, lane = tid & 31, warp = tid >> 5;
    int g = lane >> 2, t = lane & 3;
    const int lds = 3 * DIM_;
    const float scale = 0.125f;

    // ---- load Q tile (scaled + tf32-rounded) ----
    size_t qbase = ((size_t)(b * T_ + qb * QT)) * lds + h * HD_;
    for (int idx = tid; idx < QT * 16; idx += 128) {
        int r = idx >> 4, c4 = (idx & 15) * 4;
        float4 v = *(const float4*)(qkv + qbase + (size_t)r * lds + c4);
        Qs[r * AST + c4 + 0] = rtf32(v.x * scale);
        Qs[r * AST + c4 + 1] = rtf32(v.y * scale);
        Qs[r * AST + c4 + 2] = rtf32(v.z * scale);
        Qs[r * AST + c4 + 3] = rtf32(v.w * scale);
    }

    float m[2][2], l[2][2], o[2][8][4];
#pragma unroll
    for (int mt = 0; mt < 2; mt++)
#pragma unroll
        for (int hf = 0; hf < 2; hf++) { m[mt][hf] = -1e30f; l[mt][hf] = 0.f; }
#pragma unroll
    for (int mt = 0; mt < 2; mt++)
#pragma unroll
        for (int nt = 0; nt < 8; nt++)
#pragma unroll
            for (int i = 0; i < 4; i++) o[mt][nt][i] = 0.f;

    int ktiles = 2 * qb + 2;
    for (int kt = 0; kt < ktiles; kt++) {
        __syncthreads();   // prior PV reads of Kt/Vs done
        size_t kbase = ((size_t)(b * T_ + kt * KT)) * lds + DIM_ + h * HD_;
        size_t vbase = kbase + DIM_;
        // K transposed: warp lanes vary token -> conflict-free STS
        for (int idx = tid; idx < KT * 16; idx += 128) {
            int tok = idx & 63, d4 = (idx >> 6) * 4;
            float4 v = *(const float4*)(qkv + kbase + (size_t)tok * lds + d4);
            Kt[(d4 + 0) * AST + tok] = rtf32(v.x);
            Kt[(d4 + 1) * AST + tok] = rtf32(v.y);
            Kt[(d4 + 2) * AST + tok] = rtf32(v.z);
            Kt[(d4 + 3) * AST + tok] = rtf32(v.w);
        }
        // V natural layout
        for (int idx = tid; idx < KT * 16; idx += 128) {
            int tok = idx >> 4, d4 = (idx & 15) * 4;
            float4 v = *(const float4*)(qkv + vbase + (size_t)tok * lds + d4);
            v.x = rtf32(v.x); v.y = rtf32(v.y);
            v.z = rtf32(v.z); v.w = rtf32(v.w);
            *(float4*)&Vs[tok * AST + d4] = v;
        }
        if (tid < KT)
            padv[tid] = kpm[b * T_ + kt * KT + tid] ? -1e9f : 0.f;
        __syncthreads();

        // ---- S = Q K^T ----
        float s[2][8][4];
#pragma unroll
        for (int mt = 0; mt < 2; mt++)
#pragma unroll
            for (int nt = 0; nt < 8; nt++)
#pragma unroll
                for (int i = 0; i < 4; i++) s[mt][nt][i] = 0.f;

#pragma unroll
        for (int k0 = 0; k0 < 64; k0 += 8) {
            unsigned af[2][4], bf[8][2];
#pragma unroll
            for (int mt = 0; mt < 2; mt++) {
                int r = warp * 32 + mt * 16 + g;
                af[mt][0] = __float_as_uint(Qs[r * AST + k0 + t]);
                af[mt][1] = __float_as_uint(Qs[(r + 8) * AST + k0 + t]);
                af[mt][2] = __float_as_uint(Qs[r * AST + k0 + t + 4]);
                af[mt][3] = __float_as_uint(Qs[(r + 8) * AST + k0 + t + 4]);
            }
#pragma unroll
            for (int nt = 0; nt < 8; nt++) {
                int n = nt * 8 + g;
                bf[nt][0] = __float_as_uint(Kt[(k0 + t) * AST + n]);
                bf[nt][1] = __float_as_uint(Kt[(k0 + t + 4) * AST + n]);
            }
#pragma unroll
            for (int mt = 0; mt < 2; mt++)
#pragma unroll
                for (int nt = 0; nt < 8; nt++)
                    mma_tf32(s[mt][nt], af[mt], bf[nt]);
        }

        // ---- mask + online softmax (fp32) ----
        float pv0[8], pv1[8];
#pragma unroll
        for (int nt = 0; nt < 8; nt++) {
            pv0[nt] = padv[nt * 8 + t * 2];
            pv1[nt] = padv[nt * 8 + t * 2 + 1];
        }
        bool dodiag = (kt >= 2 * qb);
#pragma unroll
        for (int mt = 0; mt < 2; mt++) {
#pragma unroll
            for (int hf = 0; hf < 2; hf++) {
                int rloc = warp * 32 + mt * 16 + g + hf * 8;
                int rglob = qb * QT + rloc;
                float tmax = -1e30f;
#pragma unroll
                for (int nt = 0; nt < 8; nt++) {
                    float v0 = s[mt][nt][hf * 2]     + pv0[nt];
                    float v1 = s[mt][nt][hf * 2 + 1] + pv1[nt];
                    if (dodiag) {
                        int c0 = kt * KT + nt * 8 + t * 2;
                        if (c0     > rglob) v0 = -1e30f;
                        if (c0 + 1 > rglob) v1 = -1e30f;
                    }
                    s[mt][nt][hf * 2]     = v0;
                    s[mt][nt][hf * 2 + 1] = v1;
                    tmax = fmaxf(tmax, fmaxf(v0, v1));
                }
                tmax = fmaxf(tmax, __shfl_xor_sync(0xffffffffu, tmax, 1));
                tmax = fmaxf(tmax, __shfl_xor_sync(0xffffffffu, tmax, 2));
                float mold = m[mt][hf];
                float mnew = fmaxf(mold, tmax);
                float al = __expf(mold - mnew);
                float rsum = 0.f;
#pragma unroll
                for (int nt = 0; nt < 8; nt++) {
                    float p0 = __expf(s[mt][nt][hf * 2]     - mnew);
                    float p1 = __expf(s[mt][nt][hf * 2 + 1] - mnew);
                    rsum += p0 + p1;
                    int c = nt * 8 + t * 2;
                    Ps[rloc * AST + c]     = rtf32(p0);
                    Ps[rloc * AST + c + 1] = rtf32(p1);
                }
                rsum += __shfl_xor_sync(0xffffffffu, rsum, 1);
                rsum += __shfl_xor_sync(0xffffffffu, rsum, 2);
                m[mt][hf] = mnew;
                l[mt][hf] = l[mt][hf] * al + rsum;
#pragma unroll
                for (int nt = 0; nt < 8; nt++) {
                    o[mt][nt][hf * 2]     *= al;
                    o[mt][nt][hf * 2 + 1] *= al;
                }
            }
        }
        __syncwarp();   // Ps rows are warp-private; order STS before LDS

        // ---- O += P V ----
#pragma unroll
        for (int k0 = 0; k0 < 64; k0 += 8) {
            unsigned af[2][4], bf[8][2];
#pragma unroll
            for (int mt = 0; mt < 2; mt++) {
                int r = warp * 32 + mt * 16 + g;
                af[mt][0] = __float_as_uint(Ps[r * AST + k0 + t]);
                af[mt][1] = __float_as_uint(Ps[(r + 8) * AST + k0 + t]);
                af[mt][2] = __float_as_uint(Ps[r * AST + k0 + t + 4]);
                af[mt][3] = __float_as_uint(Ps[(r + 8) * AST + k0 + t + 4]);
            }
#pragma unroll
            for (int nt = 0; nt < 8; nt++) {
                int d = nt * 8 + g;
                bf[nt][0] = __float_as_uint(Vs[(k0 + t) * AST + d]);
                bf[nt][1] = __float_as_uint(Vs[(k0 + t + 4) * AST + d]);
            }
#pragma unroll
            for (int mt = 0; mt < 2; mt++)
#pragma unroll
                for (int nt = 0; nt < 8; nt++)
                    mma_tf32(o[mt][nt], af[mt], bf[nt]);
        }
    }

    // ---- normalize + write (tf32-rounded; feeds proj GEMM) ----
#pragma unroll
    for (int mt = 0; mt < 2; mt++) {
#pragma unroll
        for (int hf = 0; hf < 2; hf++) {
            int rloc = warp * 32 + mt * 16 + g + hf * 8;
            float invl = 1.f / l[mt][hf];
            size_t ob = ((size_t)(b * T_ + qb * QT + rloc)) * DIM_ + h * HD_;
#pragma unroll
            for (int nt = 0; nt < 8; nt++) {
                int c = nt * 8 + t * 2;
                float2 v;
                v.x = rtf32(o[mt][nt][hf * 2]     * invl);
                v.y = rtf32(o[mt][nt][hf * 2 + 1] * invl);
                *(float2*)(out + ob + c) = v;
            }
        }
    }
}

// ---------------------------------------------------------------------------
extern "C" void kernel_launch(void* const* d_in, const int* in_sizes, int n_in,
                              void* d_out, int out_size)
{
    const float* x     = (const float*)d_in[0];
    const int*   kpm   = (const int*)  d_in[1];
    const float* ln1w  = (const float*)d_in[2];
    const float* ln1b  = (const float*)d_in[3];
    const float* qkvw  = (const float*)d_in[4];
    const float* projw = (const float*)d_in[5];
    const float* projb = (const float*)d_in[6];
    const float* ln2w  = (const float*)d_in[7];
    const float* ln2b  = (const float*)d_in[8];
    const float* fc1w  = (const float*)d_in[9];
    const float* fc1b  = (const float*)d_in[10];
    const float* fc2w  = (const float*)d_in[11];
    const float* fc2b  = (const float*)d_in[12];
    float* out = (float*)d_out;

    float *h1, *qkv, *att, *x2, *h2, *f1, *wq, *wp, *w1, *w2;
    cudaGetSymbolAddress((void**)&h1,  g_h1);
    cudaGetSymbolAddress((void**)&qkv, g_qkv);
    cudaGetSymbolAddress((void**)&att, g_att);
    cudaGetSymbolAddress((void**)&x2,  g_x2);
    cudaGetSymbolAddress((void**)&h2,  g_h2);
    cudaGetSymbolAddress((void**)&f1,  g_f1);
    cudaGetSymbolAddress((void**)&wq,  g_wq);
    cudaGetSymbolAddress((void**)&wp,  g_wp);
    cudaGetSymbolAddress((void**)&w1,  g_w1);
    cudaGetSymbolAddress((void**)&w2,  g_w2);

    cudaFuncSetAttribute(attn_tc,
                         cudaFuncAttributeMaxDynamicSharedMemorySize, ATTN_SMEM);
    cudaFuncSetAttribute(gemm_tc<0>,
                         cudaFuncAttributeMaxDynamicSharedMemorySize, GEMM_SMEM);
    cudaFuncSetAttribute(gemm_tc<1>,
                         cudaFuncAttributeMaxDynamicSharedMemorySize, GEMM_SMEM);
    cudaFuncSetAttribute(gemm_tc<2>,
                         cudaFuncAttributeMaxDynamicSharedMemorySize, GEMM_SMEM);

    // 0) round weights to tf32
    round4_kernel<<<(DIM_*3*DIM_/4 + 255)/256, 256>>>(qkvw, wq, DIM_*3*DIM_/4);
    round4_kernel<<<(DIM_*DIM_/4   + 255)/256, 256>>>(projw, wp, DIM_*DIM_/4);
    round4_kernel<<<(DIM_*HID_/4   + 255)/256, 256>>>(fc1w,  w1, DIM_*HID_/4);
    round4_kernel<<<(HID_*DIM_/4   + 255)/256, 256>>>(fc2w,  w2, HID_*DIM_/4);

    // 1) LN1 (output tf32-rounded)
    ln_kernel<<<NTOK, 256>>>(x, ln1w, ln1b, h1);
    // 2) QKV GEMM
    gemm_tc<0><<<dim3(3 * DIM_ / BN, NTOK / BM), 256, GEMM_SMEM>>>(
        h1, wq, nullptr, nullptr, qkv, NTOK, 3 * DIM_, DIM_);
    // 3) Attention (tensor-core, output tf32-rounded)
    attn_tc<<<dim3(T_ / QT, NH_, B_), 128, ATTN_SMEM>>>(qkv, kpm, att);
    // 4) proj GEMM + bias + residual(x)
    gemm_tc<1><<<dim3(DIM_ / BN, NTOK / BM), 256, GEMM_SMEM>>>(
        att, wp, projb, x, x2, NTOK, DIM_, DIM_);
    // 5) LN2 (output tf32-rounded)
    ln_kernel<<<NTOK, 256>>>(x2, ln2w, ln2b, h2);
    // 6) fc1 GEMM + bias + GELU (output tf32-rounded)
    gemm_tc<2><<<dim3(HID_ / BN, NTOK / BM), 256, GEMM_SMEM>>>(
        h2, w1, fc1b, nullptr, f1, NTOK, HID_, DIM_);
    // 7) fc2 GEMM + bias + residual(x2) -> out
    gemm_tc<1><<<dim3(DIM_ / BN, NTOK / BM), 256, GEMM_SMEM>>>(
        f1, w2, fc2b, x2, out, NTOK, DIM_, HID_);
}